// round 15
// baseline (speedup 1.0000x reference)
#include <cuda_runtime.h>
#include <cuda_fp16.h>
#include <cstdint>
#include <math.h>

#define B_    1024
#define DIN_  343
#define DH_   342
#define H_    512
#define DOUT_ 311
#define NP2_  320
#define K0H_  384   // padded K (halves), layer 0: 6 chunks of 64
#define K1H_  512   // K, layers 1/2: 8 chunks of 64

// ---- scratch ----
__device__ __half g_h0[B_ * K0H_];
__device__ __half g_h1[B_ * K1H_];
__device__ __half g_h2[B_ * K1H_];
__device__ float  g_p[4][B_ * H_];   // per-control fp32 partials
__device__ float  g_coef[B_ * 4];

// ---------------- helpers ----------------
__device__ __forceinline__ float elu1(float v) { return v > 0.0f ? v : expm1f(v); }

__device__ __forceinline__ uint32_t smem_u32(const void* p) {
    uint32_t a;
    asm("{ .reg .u64 t; cvta.to.shared.u64 t, %1; cvt.u32.u64 %0, t; }" : "=r"(a) : "l"(p));
    return a;
}
__device__ __forceinline__ void cp16(uint32_t dst, const void* src) {
    asm volatile("cp.async.cg.shared.global [%0], [%1], 16;" :: "r"(dst), "l"(src) : "memory");
}
__device__ __forceinline__ void cp_commit() { asm volatile("cp.async.commit_group;" ::: "memory"); }
template <int N> __device__ __forceinline__ void cp_wait() {
    asm volatile("cp.async.wait_group %0;" :: "n"(N) : "memory");
}
__device__ __forceinline__ void ldsm4(uint32_t* r, uint32_t addr) {
    asm volatile("ldmatrix.sync.aligned.m8n8.x4.shared.b16 {%0,%1,%2,%3}, [%4];"
                 : "=r"(r[0]), "=r"(r[1]), "=r"(r[2]), "=r"(r[3]) : "r"(addr));
}
__device__ __forceinline__ void mma16(float* c, const uint32_t* a, uint32_t b0, uint32_t b1) {
    asm volatile(
        "mma.sync.aligned.m16n8k16.row.col.f32.f16.f16.f32 "
        "{%0,%1,%2,%3}, {%4,%5,%6,%7}, {%8,%9}, {%0,%1,%2,%3};"
        : "+f"(c[0]), "+f"(c[1]), "+f"(c[2]), "+f"(c[3])
        : "r"(a[0]), "r"(a[1]), "r"(a[2]), "r"(a[3]), "r"(b0), "r"(b1));
}
__device__ __forceinline__ void sts128u(uint32_t addr, uint32_t x, uint32_t y,
                                        uint32_t z, uint32_t w) {
    asm volatile("st.shared.v4.b32 [%0], {%1,%2,%3,%4};"
                 :: "r"(addr), "r"(x), "r"(y), "r"(z), "r"(w) : "memory");
}
__device__ __forceinline__ uint32_t pack2(float a, float b) {
    __half2 h = __floats2half2_rn(a, b);
    return *(uint32_t*)&h;
}

// ---------------- prep: coef + x -> g_h0 (half) ----------------
__global__ void k_z0(const float* __restrict__ x) {
    int b = blockIdx.x;
    const float* xr = x + (size_t)b * DIN_;
    float ps = 4.0f * xr[DIN_ - 1];
    float mu = ps - floorf(ps);
    int   k1 = ((int)ps) & 3;
    float m2 = mu * mu, m3 = m2 * mu;
    float a0 = -0.5f * m3 +        m2 - 0.5f * mu;
    float a1 =  1.5f * m3 - 2.5f * m2 + 1.0f;
    float a2 = -1.5f * m3 + 2.0f * m2 + 0.5f * mu;
    float a3 =  0.5f * m3 - 0.5f * m2;
    float c[4];
    c[(k1 + 3) & 3] = a0;
    c[k1]           = a1;
    c[(k1 + 1) & 3] = a2;
    c[(k1 + 2) & 3] = a3;
    if (threadIdx.x < 4) g_coef[b * 4 + threadIdx.x] = c[threadIdx.x];
    __half* z = g_h0 + (size_t)b * K0H_;
    for (int i = threadIdx.x; i < K0H_; i += blockDim.x)
        z[i] = (i < DH_) ? __float2half_rn(xr[i]) : __half(0.0f);
}

// ---------------- fp16 mma GEMM, one control per blockIdx.z -------------------
// CTA 128x64, 512 threads / 16 warps (4M x 4N), warp tile 32x16, KC=64, 3-stage.
// A via cp.async (half); B from original fp32 weights: LDG + cvt + STS half.
// Same swizzled byte layout as the proven R12 kernel.

#define NS 3
#define STG 24576u
#define NTH 512

__device__ __forceinline__ void fillA(uint32_t sdst, const __half* __restrict__ A,
                                      int bm, int KP, int k0, int t) {
#pragma unroll
    for (int j = 0; j < 2; j++) {
        int f = t + j * NTH;
        int m = f >> 3, g8 = f & 7;
        uint32_t off = (uint32_t)((((m >> 3) * 8 + g8) * 128) + (((m & 7) ^ g8) * 16));
        cp16(sdst + off, A + (size_t)(bm + m) * KP + k0 + g8 * 8);
    }
}

template <int LAYER>
__device__ __forceinline__ void ldgB(float* r, const float* __restrict__ W,
                                     int c, int bn, int k0, int t) {
    int m = t >> 3, g8 = t & 7;
    int o = bn + m;
    int col = k0 + g8 * 8;
    if (LAYER == 0) {
        const float* p = W + (size_t)(c * H_ + o) * DH_;
#pragma unroll
        for (int e = 0; e < 8; e++)
            r[e] = (col + e < DH_) ? __ldg(p + col + e) : 0.0f;
    } else if (LAYER == 1) {
        const float4* p = (const float4*)(W + (size_t)(c * H_ + o) * K1H_ + col);
        float4 v0 = p[0], v1 = p[1];
        r[0] = v0.x; r[1] = v0.y; r[2] = v0.z; r[3] = v0.w;
        r[4] = v1.x; r[5] = v1.y; r[6] = v1.z; r[7] = v1.w;
    } else {
        if (o < DOUT_) {
            const float4* p = (const float4*)(W + (size_t)(c * DOUT_ + o) * K1H_ + col);
            float4 v0 = p[0], v1 = p[1];
            r[0] = v0.x; r[1] = v0.y; r[2] = v0.z; r[3] = v0.w;
            r[4] = v1.x; r[5] = v1.y; r[6] = v1.z; r[7] = v1.w;
        } else {
#pragma unroll
            for (int e = 0; e < 8; e++) r[e] = 0.0f;
        }
    }
}

__device__ __forceinline__ void stsB(uint32_t sdst, const float* r, int t) {
    int m = t >> 3, g8 = t & 7;
    uint32_t off = (uint32_t)((((m >> 3) * 8 + g8) * 128) + (((m & 7) ^ g8) * 16));
    sts128u(sdst + off,
            pack2(r[0], r[1]), pack2(r[2], r[3]),
            pack2(r[4], r[5]), pack2(r[6], r[7]));
}

template <int LAYER>
__global__ void __launch_bounds__(NTH, 2) k_gemm(const float* __restrict__ W) {
    constexpr int KP  = (LAYER == 0) ? K0H_ : K1H_;
    constexpr int NIT = KP / 64;
    constexpr int NP  = (LAYER == 2) ? NP2_ : H_;
    const __half* __restrict__ A = (LAYER == 0) ? g_h0 : (LAYER == 1 ? g_h1 : g_h2);

    extern __shared__ float smem[];
    uint32_t sbase = smem_u32(smem);

    const int t = threadIdx.x, lane = t & 31, wid = t >> 5;
    const int wm = (wid >> 2) * 32, wn = (wid & 3) * 16;
    const int bm = blockIdx.y * 128, bn = blockIdx.x * 64;
    const int c = blockIdx.z;
    float* __restrict__ dst = g_p[c];
    const int g = lane >> 3, r = lane & 7;
    const int ga = g & 1, gb = g >> 1;
    const int wm8 = wm >> 3, wn8 = wn >> 3;

    float acc[2][2][4] = {};
    float rB[8];

    // prologue (stages 0,1)
    ldgB<LAYER>(rB, W, c, bn, 0, t);
    stsB(sbase + 16384u, rB, t);
    fillA(sbase, A, bm, KP, 0, t);
    cp_commit();
    fillA(sbase + STG, A, bm, KP, 64, t);
    cp_commit();
    ldgB<LAYER>(rB, W, c, bn, 64, t);

#pragma unroll 1
    for (int it = 0; it < NIT; it++) {
        int s = it % NS;
        cp_wait<NS - 2>();
        __syncthreads();
        if (it + 2 < NIT)
            fillA(sbase + (uint32_t)((it + 2) % NS) * STG, A, bm, KP, (it + 2) * 64, t);
        cp_commit();

        uint32_t sa  = sbase + (uint32_t)s * STG;
        uint32_t sbB = sa + 16384u;
#pragma unroll
        for (int ki2 = 0; ki2 < 4; ki2++) {
            int k4a = ki2 * 2 + gb;
            int k4b = ki2 * 2 + ga;
            uint32_t a0[4], a1[4], b0[4];
            ldsm4(a0, sa  + (uint32_t)((((wm8 + ga) * 8 + k4a) * 128) + ((r ^ k4a) * 16)));
            ldsm4(a1, sa  + (uint32_t)((((wm8 + 2 + ga) * 8 + k4a) * 128) + ((r ^ k4a) * 16)));
            ldsm4(b0, sbB + (uint32_t)((((wn8 + gb) * 8 + k4b) * 128) + ((r ^ k4b) * 16)));
            mma16(acc[0][0], a0, b0[0], b0[1]);
            mma16(acc[0][1], a0, b0[2], b0[3]);
            mma16(acc[1][0], a1, b0[0], b0[1]);
            mma16(acc[1][1], a1, b0[2], b0[3]);
        }

        if (it + 1 < NIT) stsB(sbase + (uint32_t)((it + 1) % NS) * STG + 16384u, rB, t);
        if (it + 2 < NIT) ldgB<LAYER>(rB, W, c, bn, (it + 2) * 64, t);
    }

    // store coef-scaled fp32 partials
#pragma unroll
    for (int mt = 0; mt < 2; mt++) {
        int m0 = bm + wm + mt * 16 + (lane >> 2);
        int m1 = m0 + 8;
        float cs0 = g_coef[m0 * 4 + c];
        float cs1 = g_coef[m1 * 4 + c];
#pragma unroll
        for (int nt = 0; nt < 2; nt++) {
            int n = bn + wn + nt * 8 + (lane & 3) * 2;
            *(float2*)&dst[(size_t)m0 * NP + n] =
                make_float2(acc[mt][nt][0] * cs0, acc[mt][nt][1] * cs0);
            *(float2*)&dst[(size_t)m1 * NP + n] =
                make_float2(acc[mt][nt][2] * cs1, acc[mt][nt][3] * cs1);
        }
    }
}

// ---- epilogue: sum 4 partials + coef-weighted bias; ELU -> half, or final ----
template <int LAYER>
__global__ void __launch_bounds__(256) k_ep(const float* __restrict__ bias,
                                            float* __restrict__ out_final) {
    int tx = threadIdx.x;
    int b = blockIdx.x * 2 + (tx >> 7);
    int tr = tx & 127;
    float4 cf = *(const float4*)&g_coef[b * 4];
    float cc[4] = {cf.x, cf.y, cf.z, cf.w};
    if (LAYER < 2) {
        int n = tr * 4;
        float4 v0 = *(const float4*)&g_p[0][(size_t)b * H_ + n];
        float4 v1 = *(const float4*)&g_p[1][(size_t)b * H_ + n];
        float4 v2 = *(const float4*)&g_p[2][(size_t)b * H_ + n];
        float4 v3 = *(const float4*)&g_p[3][(size_t)b * H_ + n];
        float s0 = v0.x + v1.x + v2.x + v3.x;
        float s1 = v0.y + v1.y + v2.y + v3.y;
        float s2 = v0.z + v1.z + v2.z + v3.z;
        float s3 = v0.w + v1.w + v2.w + v3.w;
#pragma unroll
        for (int ct = 0; ct < 4; ct++) {
            float4 bb = *(const float4*)&bias[ct * H_ + n];
            s0 += cc[ct] * bb.x; s1 += cc[ct] * bb.y;
            s2 += cc[ct] * bb.z; s3 += cc[ct] * bb.w;
        }
        __half* zn = ((LAYER == 0) ? g_h1 : g_h2) + (size_t)b * K1H_;
        __half2 h01 = __floats2half2_rn(elu1(s0), elu1(s1));
        __half2 h23 = __floats2half2_rn(elu1(s2), elu1(s3));
        *(uint32_t*)(zn + n)     = *(uint32_t*)&h01;
        *(uint32_t*)(zn + n + 2) = *(uint32_t*)&h23;
    } else {
        float* o = out_final + (size_t)b * DOUT_;
        for (int n = tr; n < DOUT_; n += 128) {
            float s = g_p[0][(size_t)b * NP2_ + n] + g_p[1][(size_t)b * NP2_ + n]
                    + g_p[2][(size_t)b * NP2_ + n] + g_p[3][(size_t)b * NP2_ + n];
#pragma unroll
            for (int ct = 0; ct < 4; ct++) s += cc[ct] * bias[ct * DOUT_ + n];
            o[n] = s;
        }
    }
}

// ---------------- launch ----------------
extern "C" void kernel_launch(void* const* d_in, const int* in_sizes, int n_in,
                              void* d_out, int out_size) {
    const float* x  = (const float*)d_in[0];
    const float* W0 = (const float*)d_in[1];
    const float* W1 = (const float*)d_in[2];
    const float* W2 = (const float*)d_in[3];
    const float* b0 = (const float*)d_in[4];
    const float* b1 = (const float*)d_in[5];
    const float* b2 = (const float*)d_in[6];
    float* out = (float*)d_out;

    static int smem_set = 0;
    if (!smem_set) {
        cudaFuncSetAttribute(k_gemm<0>, cudaFuncAttributeMaxDynamicSharedMemorySize, NS * STG);
        cudaFuncSetAttribute(k_gemm<1>, cudaFuncAttributeMaxDynamicSharedMemorySize, NS * STG);
        cudaFuncSetAttribute(k_gemm<2>, cudaFuncAttributeMaxDynamicSharedMemorySize, NS * STG);
        smem_set = 1;
    }

    k_z0<<<B_, 128>>>(x);

    k_gemm<0><<<dim3(8, 8, 4), NTH, NS * STG>>>(W0);
    k_ep<0><<<B_ / 2, 256>>>(b0, nullptr);
    k_gemm<1><<<dim3(8, 8, 4), NTH, NS * STG>>>(W1);
    k_ep<1><<<B_ / 2, 256>>>(b1, nullptr);
    k_gemm<2><<<dim3(5, 8, 4), NTH, NS * STG>>>(W2);
    k_ep<2><<<B_ / 2, 256>>>(b2, out);
}

// round 16
// speedup vs baseline: 1.2111x; 1.2111x over previous
#include <cuda_runtime.h>
#include <cuda_fp16.h>
#include <cstdint>
#include <math.h>

#define B_    1024
#define DIN_  343
#define DH_   342
#define H_    512
#define DOUT_ 311
#define NP2_  320
#define K0H_  384   // padded K (halves), layer 0: 6 chunks of 64
#define K1H_  512   // K, layers 1/2: 8 chunks of 64

// ---- scratch ----
__device__ __half g_h0[B_ * K0H_];
__device__ __half g_h1[B_ * K1H_];
__device__ __half g_h2[B_ * K1H_];
__device__ float  g_p[4][B_ * H_];   // per-control fp32 partials
__device__ float  g_coef[B_ * 4];

// ---------------- helpers ----------------
__device__ __forceinline__ float elu1(float v) { return v > 0.0f ? v : expm1f(v); }

__device__ __forceinline__ uint32_t smem_u32(const void* p) {
    uint32_t a;
    asm("{ .reg .u64 t; cvta.to.shared.u64 t, %1; cvt.u32.u64 %0, t; }" : "=r"(a) : "l"(p));
    return a;
}
__device__ __forceinline__ void cp16(uint32_t dst, const void* src) {
    asm volatile("cp.async.cg.shared.global [%0], [%1], 16;" :: "r"(dst), "l"(src) : "memory");
}
__device__ __forceinline__ void cp_commit() { asm volatile("cp.async.commit_group;" ::: "memory"); }
template <int N> __device__ __forceinline__ void cp_wait() {
    asm volatile("cp.async.wait_group %0;" :: "n"(N) : "memory");
}
__device__ __forceinline__ void ldsm4(uint32_t* r, uint32_t addr) {
    asm volatile("ldmatrix.sync.aligned.m8n8.x4.shared.b16 {%0,%1,%2,%3}, [%4];"
                 : "=r"(r[0]), "=r"(r[1]), "=r"(r[2]), "=r"(r[3]) : "r"(addr));
}
__device__ __forceinline__ void mma16(float* c, const uint32_t* a, uint32_t b0, uint32_t b1) {
    asm volatile(
        "mma.sync.aligned.m16n8k16.row.col.f32.f16.f16.f32 "
        "{%0,%1,%2,%3}, {%4,%5,%6,%7}, {%8,%9}, {%0,%1,%2,%3};"
        : "+f"(c[0]), "+f"(c[1]), "+f"(c[2]), "+f"(c[3])
        : "r"(a[0]), "r"(a[1]), "r"(a[2]), "r"(a[3]), "r"(b0), "r"(b1));
}
__device__ __forceinline__ void sts128u(uint32_t addr, uint32_t x, uint32_t y,
                                        uint32_t z, uint32_t w) {
    asm volatile("st.shared.v4.b32 [%0], {%1,%2,%3,%4};"
                 :: "r"(addr), "r"(x), "r"(y), "r"(z), "r"(w) : "memory");
}
__device__ __forceinline__ uint32_t pack2(float a, float b) {
    __half2 h = __floats2half2_rn(a, b);
    return *(uint32_t*)&h;
}

// ---------------- prep: coef + x -> g_h0 (half) ----------------
__global__ void k_z0(const float* __restrict__ x) {
    int b = blockIdx.x;
    const float* xr = x + (size_t)b * DIN_;
    float ps = 4.0f * xr[DIN_ - 1];
    float mu = ps - floorf(ps);
    int   k1 = ((int)ps) & 3;
    float m2 = mu * mu, m3 = m2 * mu;
    float a0 = -0.5f * m3 +        m2 - 0.5f * mu;
    float a1 =  1.5f * m3 - 2.5f * m2 + 1.0f;
    float a2 = -1.5f * m3 + 2.0f * m2 + 0.5f * mu;
    float a3 =  0.5f * m3 - 0.5f * m2;
    float c[4];
    c[(k1 + 3) & 3] = a0;
    c[k1]           = a1;
    c[(k1 + 1) & 3] = a2;
    c[(k1 + 2) & 3] = a3;
    if (threadIdx.x < 4) g_coef[b * 4 + threadIdx.x] = c[threadIdx.x];
    __half* z = g_h0 + (size_t)b * K0H_;
    for (int i = threadIdx.x; i < K0H_; i += blockDim.x)
        z[i] = (i < DH_) ? __float2half_rn(xr[i]) : __half(0.0f);
}

// ---------------- fp16 mma GEMM, one control per blockIdx.z -------------------
// CTA 128x128, 512 threads / 16 warps (4M x 4N), warp tile 32x32, KC=64,
// 3-stage. A via cp.async (half); B from original fp32 weights (LDG+cvt+STS).
// Stage: A 128x64h = 16KB + B 128x64h = 16KB -> 32KB. Same swizzled layout.

#define NS 3
#define STG 32768u
#define NTH 512

__device__ __forceinline__ void fillA(uint32_t sdst, const __half* __restrict__ A,
                                      int bm, int KP, int k0, int t) {
#pragma unroll
    for (int j = 0; j < 2; j++) {
        int f = t + j * NTH;
        int m = f >> 3, g8 = f & 7;
        uint32_t off = (uint32_t)((((m >> 3) * 8 + g8) * 128) + (((m & 7) ^ g8) * 16));
        cp16(sdst + off, A + (size_t)(bm + m) * KP + k0 + g8 * 8);
    }
}

template <int LAYER>
__device__ __forceinline__ void ldgB(float* r, const float* __restrict__ W,
                                     int c, int bn, int k0, int t) {
#pragma unroll
    for (int j = 0; j < 2; j++) {
        int f = t + j * NTH;
        int m = f >> 3, g8 = f & 7;
        int o = bn + m;
        int col = k0 + g8 * 8;
        if (LAYER == 0) {
            const float* p = W + (size_t)(c * H_ + o) * DH_;
#pragma unroll
            for (int e = 0; e < 8; e++)
                r[j * 8 + e] = (col + e < DH_) ? __ldg(p + col + e) : 0.0f;
        } else if (LAYER == 1) {
            const float4* p = (const float4*)(W + (size_t)(c * H_ + o) * K1H_ + col);
            float4 v0 = p[0], v1 = p[1];
            r[j * 8 + 0] = v0.x; r[j * 8 + 1] = v0.y; r[j * 8 + 2] = v0.z; r[j * 8 + 3] = v0.w;
            r[j * 8 + 4] = v1.x; r[j * 8 + 5] = v1.y; r[j * 8 + 6] = v1.z; r[j * 8 + 7] = v1.w;
        } else {
            if (o < DOUT_) {
                const float4* p = (const float4*)(W + (size_t)(c * DOUT_ + o) * K1H_ + col);
                float4 v0 = p[0], v1 = p[1];
                r[j * 8 + 0] = v0.x; r[j * 8 + 1] = v0.y; r[j * 8 + 2] = v0.z; r[j * 8 + 3] = v0.w;
                r[j * 8 + 4] = v1.x; r[j * 8 + 5] = v1.y; r[j * 8 + 6] = v1.z; r[j * 8 + 7] = v1.w;
            } else {
#pragma unroll
                for (int e = 0; e < 8; e++) r[j * 8 + e] = 0.0f;
            }
        }
    }
}

__device__ __forceinline__ void stsB(uint32_t sdst, const float* r, int t) {
#pragma unroll
    for (int j = 0; j < 2; j++) {
        int f = t + j * NTH;
        int m = f >> 3, g8 = f & 7;
        uint32_t off = (uint32_t)((((m >> 3) * 8 + g8) * 128) + (((m & 7) ^ g8) * 16));
        sts128u(sdst + off,
                pack2(r[j * 8 + 0], r[j * 8 + 1]), pack2(r[j * 8 + 2], r[j * 8 + 3]),
                pack2(r[j * 8 + 4], r[j * 8 + 5]), pack2(r[j * 8 + 6], r[j * 8 + 7]));
    }
}

template <int LAYER>
__global__ void __launch_bounds__(NTH) k_gemm(const float* __restrict__ W) {
    constexpr int KP  = (LAYER == 0) ? K0H_ : K1H_;
    constexpr int NIT = KP / 64;
    constexpr int NP  = (LAYER == 2) ? NP2_ : H_;
    const __half* __restrict__ A = (LAYER == 0) ? g_h0 : (LAYER == 1 ? g_h1 : g_h2);

    extern __shared__ float smem[];
    uint32_t sbase = smem_u32(smem);

    const int t = threadIdx.x, lane = t & 31, wid = t >> 5;
    const int wm = (wid >> 2) * 32, wn = (wid & 3) * 32;
    const int bm = blockIdx.y * 128, bn = blockIdx.x * 128;
    const int c = blockIdx.z;
    float* __restrict__ dst = g_p[c];
    const int g = lane >> 3, r = lane & 7;
    const int ga = g & 1, gb = g >> 1;
    const int wm8 = wm >> 3, wn8 = wn >> 3;

    float acc[2][4][4] = {};
    float rB[16];

    // prologue (stages 0,1)
    ldgB<LAYER>(rB, W, c, bn, 0, t);
    stsB(sbase + 16384u, rB, t);
    fillA(sbase, A, bm, KP, 0, t);
    cp_commit();
    fillA(sbase + STG, A, bm, KP, 64, t);
    cp_commit();
    ldgB<LAYER>(rB, W, c, bn, 64, t);

#pragma unroll 1
    for (int it = 0; it < NIT; it++) {
        int s = it % NS;
        cp_wait<NS - 2>();
        __syncthreads();
        if (it + 2 < NIT)
            fillA(sbase + (uint32_t)((it + 2) % NS) * STG, A, bm, KP, (it + 2) * 64, t);
        cp_commit();

        uint32_t sa  = sbase + (uint32_t)s * STG;
        uint32_t sbB = sa + 16384u;
#pragma unroll
        for (int ki2 = 0; ki2 < 4; ki2++) {
            int k4a = ki2 * 2 + gb;
            int k4b = ki2 * 2 + ga;
            uint32_t a0[4], a1[4], b0[4], b1[4];
            ldsm4(a0, sa  + (uint32_t)((((wm8 + ga) * 8 + k4a) * 128) + ((r ^ k4a) * 16)));
            ldsm4(a1, sa  + (uint32_t)((((wm8 + 2 + ga) * 8 + k4a) * 128) + ((r ^ k4a) * 16)));
            ldsm4(b0, sbB + (uint32_t)((((wn8 + gb) * 8 + k4b) * 128) + ((r ^ k4b) * 16)));
            ldsm4(b1, sbB + (uint32_t)((((wn8 + 2 + gb) * 8 + k4b) * 128) + ((r ^ k4b) * 16)));
            mma16(acc[0][0], a0, b0[0], b0[1]);
            mma16(acc[0][1], a0, b0[2], b0[3]);
            mma16(acc[0][2], a0, b1[0], b1[1]);
            mma16(acc[0][3], a0, b1[2], b1[3]);
            mma16(acc[1][0], a1, b0[0], b0[1]);
            mma16(acc[1][1], a1, b0[2], b0[3]);
            mma16(acc[1][2], a1, b1[0], b1[1]);
            mma16(acc[1][3], a1, b1[2], b1[3]);
        }

        if (it + 1 < NIT) stsB(sbase + (uint32_t)((it + 1) % NS) * STG + 16384u, rB, t);
        if (it + 2 < NIT) ldgB<LAYER>(rB, W, c, bn, (it + 2) * 64, t);
    }

    // store coef-scaled fp32 partials
#pragma unroll
    for (int mt = 0; mt < 2; mt++) {
        int m0 = bm + wm + mt * 16 + (lane >> 2);
        int m1 = m0 + 8;
        float cs0 = g_coef[m0 * 4 + c];
        float cs1 = g_coef[m1 * 4 + c];
#pragma unroll
        for (int nt = 0; nt < 4; nt++) {
            int n = bn + wn + nt * 8 + (lane & 3) * 2;
            if (LAYER == 2 && n >= NP2_) continue;
            *(float2*)&dst[(size_t)m0 * NP + n] =
                make_float2(acc[mt][nt][0] * cs0, acc[mt][nt][1] * cs0);
            *(float2*)&dst[(size_t)m1 * NP + n] =
                make_float2(acc[mt][nt][2] * cs1, acc[mt][nt][3] * cs1);
        }
    }
}

// ---- epilogue: sum 4 partials + coef-weighted bias; ELU -> half, or final ----
template <int LAYER>
__global__ void __launch_bounds__(256) k_ep(const float* __restrict__ bias,
                                            float* __restrict__ out_final) {
    int tx = threadIdx.x;
    int b = blockIdx.x * 2 + (tx >> 7);
    int tr = tx & 127;
    float4 cf = *(const float4*)&g_coef[b * 4];
    float cc[4] = {cf.x, cf.y, cf.z, cf.w};
    if (LAYER < 2) {
        int n = tr * 4;
        float4 v0 = *(const float4*)&g_p[0][(size_t)b * H_ + n];
        float4 v1 = *(const float4*)&g_p[1][(size_t)b * H_ + n];
        float4 v2 = *(const float4*)&g_p[2][(size_t)b * H_ + n];
        float4 v3 = *(const float4*)&g_p[3][(size_t)b * H_ + n];
        float s0 = v0.x + v1.x + v2.x + v3.x;
        float s1 = v0.y + v1.y + v2.y + v3.y;
        float s2 = v0.z + v1.z + v2.z + v3.z;
        float s3 = v0.w + v1.w + v2.w + v3.w;
#pragma unroll
        for (int ct = 0; ct < 4; ct++) {
            float4 bb = *(const float4*)&bias[ct * H_ + n];
            s0 += cc[ct] * bb.x; s1 += cc[ct] * bb.y;
            s2 += cc[ct] * bb.z; s3 += cc[ct] * bb.w;
        }
        __half* zn = ((LAYER == 0) ? g_h1 : g_h2) + (size_t)b * K1H_;
        __half2 h01 = __floats2half2_rn(elu1(s0), elu1(s1));
        __half2 h23 = __floats2half2_rn(elu1(s2), elu1(s3));
        *(uint32_t*)(zn + n)     = *(uint32_t*)&h01;
        *(uint32_t*)(zn + n + 2) = *(uint32_t*)&h23;
    } else {
        float* o = out_final + (size_t)b * DOUT_;
        for (int n = tr; n < DOUT_; n += 128) {
            float s = g_p[0][(size_t)b * NP2_ + n] + g_p[1][(size_t)b * NP2_ + n]
                    + g_p[2][(size_t)b * NP2_ + n] + g_p[3][(size_t)b * NP2_ + n];
#pragma unroll
            for (int ct = 0; ct < 4; ct++) s += cc[ct] * bias[ct * DOUT_ + n];
            o[n] = s;
        }
    }
}

// ---------------- launch ----------------
extern "C" void kernel_launch(void* const* d_in, const int* in_sizes, int n_in,
                              void* d_out, int out_size) {
    const float* x  = (const float*)d_in[0];
    const float* W0 = (const float*)d_in[1];
    const float* W1 = (const float*)d_in[2];
    const float* W2 = (const float*)d_in[3];
    const float* b0 = (const float*)d_in[4];
    const float* b1 = (const float*)d_in[5];
    const float* b2 = (const float*)d_in[6];
    float* out = (float*)d_out;

    static int smem_set = 0;
    if (!smem_set) {
        cudaFuncSetAttribute(k_gemm<0>, cudaFuncAttributeMaxDynamicSharedMemorySize, NS * STG);
        cudaFuncSetAttribute(k_gemm<1>, cudaFuncAttributeMaxDynamicSharedMemorySize, NS * STG);
        cudaFuncSetAttribute(k_gemm<2>, cudaFuncAttributeMaxDynamicSharedMemorySize, NS * STG);
        smem_set = 1;
    }

    k_z0<<<B_, 128>>>(x);

    k_gemm<0><<<dim3(4, 8, 4), NTH, NS * STG>>>(W0);
    k_ep<0><<<B_ / 2, 256>>>(b0, nullptr);
    k_gemm<1><<<dim3(4, 8, 4), NTH, NS * STG>>>(W1);
    k_ep<1><<<B_ / 2, 256>>>(b1, nullptr);
    k_gemm<2><<<dim3(3, 8, 4), NTH, NS * STG>>>(W2);
    k_ep<2><<<B_ / 2, 256>>>(b2, out);
}